// round 10
// baseline (speedup 1.0000x reference)
#include <cuda_runtime.h>
#include <cuda_bf16.h>
#include <cstdint>
#include <cstddef>

#define NN 50000
#define NE 600000
#define DD 128
#define NSTEP 5
#define MT 391    // ceil(NN/128)
#define CSTR 128  // padded CSR stride (E[deg]=12)

// ---------------- device scratch ----------------
static __device__ float g_cnt[4 * NN];
static __device__ int g_fillc[NN];
static __device__ uint32_t g_csr[(size_t)NN * CSTR];
static __device__ float g_hbuf[(size_t)2 * NN * DD];
static __device__ float g_gc[(size_t)NN * 512];   // [rsum|zsum|i_n|h_n]
// A-combined bf16 planes: segs 0-3 = per-type agg, seg 4 = h
static __device__ __align__(16) __nv_bfloat16 g_ah[(size_t)5 * NN * DD];
static __device__ __align__(16) __nv_bfloat16 g_al[(size_t)5 * NN * DD];
static __device__ __align__(16) __nv_bfloat16 g_wc_hi[512 * 640];
static __device__ __align__(16) __nv_bfloat16 g_wc_lo[512 * 640];
static __device__ float g_blinw[4 * 384];

// ---------------- helpers ----------------
__device__ __forceinline__ uint32_t s2u(const void* p) {
    uint32_t a;
    asm("{ .reg .u64 t; cvta.to.shared.u64 t, %1; cvt.u32.u64 %0, t; }" : "=r"(a) : "l"(p));
    return a;
}
__device__ __forceinline__ void cpa16(uint32_t dst, const void* src) {
    asm volatile("cp.async.cg.shared.global [%0], [%1], 16;" :: "r"(dst), "l"(src));
}
__device__ __forceinline__ void cpa16z(uint32_t dst, const void* src) {
    asm volatile("cp.async.cg.shared.global [%0], [%1], 16, 0;" :: "r"(dst), "l"(src));
}
__device__ __forceinline__ void ldmx4(uint32_t* r, uint32_t addr) {
    asm volatile("ldmatrix.sync.aligned.m8n8.x4.shared.b16 {%0,%1,%2,%3}, [%4];"
                 : "=r"(r[0]), "=r"(r[1]), "=r"(r[2]), "=r"(r[3]) : "r"(addr));
}
__device__ __forceinline__ void mma16816(float* d, const uint32_t* a, const uint32_t* b) {
    asm volatile(
        "mma.sync.aligned.m16n8k16.row.col.f32.bf16.bf16.f32 "
        "{%0,%1,%2,%3}, {%4,%5,%6,%7}, {%8,%9}, {%0,%1,%2,%3};"
        : "+f"(d[0]), "+f"(d[1]), "+f"(d[2]), "+f"(d[3])
        : "r"(a[0]), "r"(a[1]), "r"(a[2]), "r"(a[3]), "r"(b[0]), "r"(b[1]));
}
// float4 -> 4 bf16 hi (uint2) + 4 bf16 lo (uint2)
__device__ __forceinline__ void split4(float4 v, uint2& hi, uint2& lo) {
    union { __nv_bfloat16 b[4]; uint2 u; } uh, ul;
    float f[4] = {v.x, v.y, v.z, v.w};
#pragma unroll
    for (int i = 0; i < 4; i++) {
        __nv_bfloat16 h = __float2bfloat16(f[i]);
        uh.b[i] = h;
        ul.b[i] = __float2bfloat16(f[i] - __bfloat162float(h));
    }
    hi = uh.u;
    lo = ul.u;
}

// ---------------- launch #1: zero counters + weight precompute ----------------
__global__ void k_prep0(const float* __restrict__ wih, const float* __restrict__ Wlin,
                        const float* __restrict__ whh, const float* __restrict__ blin) {
    int idx = blockIdx.x * blockDim.x + threadIdx.x;
    if (idx < 4 * NN) g_cnt[idx] = 0.f;
    if (idx < NN) g_fillc[idx] = 0;
    if (idx < 196608) {  // Wcomb rows 0-383, cols 0-511: (wih @ Wlin_k), hi/lo
        int j = idx >> 9, kk = idx & 511, kt = kk >> 7, d = kk & 127;
        const float* wr = wih + j * 128;
        const float* wl = Wlin + (size_t)kt * 16384 + d;
        float s = 0.f;
#pragma unroll 8
        for (int d2 = 0; d2 < 128; d2++) s += wr[d2] * wl[(size_t)d2 * 128];
        __nv_bfloat16 h = __float2bfloat16(s);
        g_wc_hi[(size_t)j * 640 + kk] = h;
        g_wc_lo[(size_t)j * 640 + kk] = __float2bfloat16(s - __bfloat162float(h));
        return;
    }
    int t0 = idx - 196608;
    if (t0 < 32768) {            // rows 0-255 (r,z) cols 512-639 <- whh rows 0-255
        int j = t0 >> 7, c = t0 & 127;
        float x = whh[t0];
        __nv_bfloat16 h = __float2bfloat16(x);
        g_wc_hi[(size_t)j * 640 + 512 + c] = h;
        g_wc_lo[(size_t)j * 640 + 512 + c] = __float2bfloat16(x - __bfloat162float(h));
    } else if (t0 < 49152) {     // rows 384-511 (h_n) <- whh rows 256-383
        int t = t0 - 32768;
        int j = t >> 7, c = t & 127;
        float x = whh[(256 + j) * 128 + c];
        __nv_bfloat16 h = __float2bfloat16(x);
        g_wc_hi[(size_t)(384 + j) * 640 + 512 + c] = h;
        g_wc_lo[(size_t)(384 + j) * 640 + 512 + c] =
            __float2bfloat16(x - __bfloat162float(h));
    } else if (t0 < 50688) {     // blw[k][j] = blin[k] . wih[j]
        int t = t0 - 49152;
        int k = t / 384, j = t % 384;
        float s = 0.f;
        for (int d = 0; d < 128; d++) s += blin[k * 128 + d] * wih[j * 128 + d];
        g_blinw[k * 384 + j] = s;
    }
}

// ---------------- launch #2: CSR build + per-type degree counts ----------------
__global__ void k_build(const int* __restrict__ src, const int* __restrict__ dst,
                        const int* __restrict__ et) {
    int e = blockIdx.x * blockDim.x + threadIdx.x;
    if (e >= NE) return;
    int d = dst[e];
    int k = et[e] - 1;
    atomicAdd(&g_cnt[k * NN + d], 1.0f);
    int pos = atomicAdd(&g_fillc[d], 1);
    if (pos < CSTR)
        g_csr[(size_t)d * CSTR + pos] = (uint32_t)src[e] | ((uint32_t)k << 16);
}

// ---------------- per-step gather: warp per node, writes bf16 hi/lo planes ----
__global__ __launch_bounds__(256)
void k_gather(const float* __restrict__ h) {
    int v = (blockIdx.x * blockDim.x + threadIdx.x) >> 5;
    int lane = threadIdx.x & 31;
    if (v >= NN) return;
    int deg = g_fillc[v];
    const uint32_t* row = &g_csr[(size_t)v * CSTR];
    const float4* h4 = (const float4*)h;
    float4 a0 = make_float4(0, 0, 0, 0), a1 = a0, a2 = a0, a3 = a0;
    for (int base = 0; base < deg; base += 32) {
        uint32_t pk = (base + lane < deg) ? row[base + lane] : 0u;
        int lim = min(32, deg - base);
        for (int j = 0; j < lim; j++) {
            uint32_t p = __shfl_sync(0xFFFFFFFFu, pk, j);
            int s = p & 0xFFFF;
            int k = p >> 16;
            float4 hv = h4[(size_t)s * 32 + lane];
            switch (k) {
                case 0: a0.x += hv.x; a0.y += hv.y; a0.z += hv.z; a0.w += hv.w; break;
                case 1: a1.x += hv.x; a1.y += hv.y; a1.z += hv.z; a1.w += hv.w; break;
                case 2: a2.x += hv.x; a2.y += hv.y; a2.z += hv.z; a2.w += hv.w; break;
                default: a3.x += hv.x; a3.y += hv.y; a3.z += hv.z; a3.w += hv.w; break;
            }
        }
    }
    float4 acc[4] = {a0, a1, a2, a3};
#pragma unroll
    for (int k = 0; k < 4; k++) {
        uint2 hi, lo;
        split4(acc[k], hi, lo);
        ((uint2*)(g_ah + ((size_t)k * NN + v) * DD))[lane] = hi;
        ((uint2*)(g_al + ((size_t)k * NN + v) * DD))[lane] = lo;
    }
    // own h row -> seg 4 (h in bf16 hi/lo for the GEMM)
    {
        uint2 hi, lo;
        split4(h4[(size_t)v * 32 + lane], hi, lo);
        ((uint2*)(g_ah + ((size_t)4 * NN + v) * DD))[lane] = hi;
        ((uint2*)(g_al + ((size_t)4 * NN + v) * DD))[lane] = lo;
    }
}

// ---------------- merged 3xBF16 GEMM, all-cp.async 3-stage ring ----------------
// C[i0..+128, j0..+128] = Acomb @ Wcomb^T; jt0,1: K=[0,640); jt2: [0,512); jt3: [512,640)
// smem stage (32KB): A rows 0-127 @0, B rows 0-127 @16384; row = 128B [32k hi | 32k lo],
// SW128 XOR swizzle: col_byte ^= (row&7)<<4
#define KC 32
#define STG_B 16384
#define STG 32768
#define SMEM_SZ 98304

__global__ __launch_bounds__(256, 2)
void k_gemm(const __nv_bfloat16* __restrict__ Ah, const __nv_bfloat16* __restrict__ Al,
            const __nv_bfloat16* __restrict__ Wh, const __nv_bfloat16* __restrict__ Wl,
            float* __restrict__ Cout) {
    extern __shared__ char sm[];
    uint32_t smb = s2u(sm);
    int tid = threadIdx.x, wid = tid >> 5, lane = tid & 31;
    int jt = blockIdx.x;
    int i0 = blockIdx.y * 128, j0 = jt * 128;
    int kstart = (jt == 3) ? 512 : 0;
    int nCh = (jt == 2) ? 16 : ((jt == 3) ? 4 : 20);
    int wm = (wid & 1) * 64, wn = (wid >> 1) * 32;
    int cRow = tid >> 1, cHf = tid & 1;
    int gr0 = i0 + cRow;
    uint32_t cSwz = (uint32_t)((cRow & 7) << 4);
    uint32_t cD0 = (uint32_t)cRow * 128 + (((uint32_t)cHf * 32) ^ cSwz);
    uint32_t cD1 = (uint32_t)cRow * 128 + (((uint32_t)cHf * 32 + 16) ^ cSwz);
    uint32_t cD2 = (uint32_t)cRow * 128 + ((64 + (uint32_t)cHf * 32) ^ cSwz);
    uint32_t cD3 = (uint32_t)cRow * 128 + ((64 + (uint32_t)cHf * 32 + 16) ^ cSwz);

    float acc[4][4][4];
#pragma unroll
    for (int a = 0; a < 4; a++)
#pragma unroll
        for (int b = 0; b < 4; b++)
#pragma unroll
            for (int c = 0; c < 4; c++) acc[a][b][c] = 0.f;

#define CPST(ch, stg)                                                               \
    {                                                                               \
        int kc_ = kstart + (ch) * KC;                                               \
        int seg_ = kc_ >> 7, kl_ = kc_ & 127;                                       \
        uint32_t sb_ = smb + (uint32_t)(stg) * STG;                                 \
        const __nv_bfloat16* ah_ =                                                  \
            Ah + ((size_t)seg_ * NN + (gr0 < NN ? gr0 : 0)) * DD + kl_ + cHf * 16;  \
        const __nv_bfloat16* al_ =                                                  \
            Al + ((size_t)seg_ * NN + (gr0 < NN ? gr0 : 0)) * DD + kl_ + cHf * 16;  \
        if (gr0 < NN) {                                                             \
            cpa16(sb_ + cD0, ah_);                                                  \
            cpa16(sb_ + cD1, ah_ + 8);                                              \
            cpa16(sb_ + cD2, al_);                                                  \
            cpa16(sb_ + cD3, al_ + 8);                                              \
        } else {                                                                    \
            cpa16z(sb_ + cD0, ah_);                                                 \
            cpa16z(sb_ + cD1, ah_ + 8);                                             \
            cpa16z(sb_ + cD2, al_);                                                 \
            cpa16z(sb_ + cD3, al_ + 8);                                             \
        }                                                                           \
        const __nv_bfloat16* wh_ = Wh + (size_t)(j0 + cRow) * 640 + kc_ + cHf * 16; \
        const __nv_bfloat16* wl_ = Wl + (size_t)(j0 + cRow) * 640 + kc_ + cHf * 16; \
        cpa16(sb_ + STG_B + cD0, wh_);                                              \
        cpa16(sb_ + STG_B + cD1, wh_ + 8);                                          \
        cpa16(sb_ + STG_B + cD2, wl_);                                              \
        cpa16(sb_ + STG_B + cD3, wl_ + 8);                                          \
        asm volatile("cp.async.commit_group;");                                     \
    }

    CPST(0, 0);
    CPST(1, 1);

    // per-lane ldmatrix bases
    int rowA = wm + (lane & 15);
    uint32_t swzA = (uint32_t)((rowA & 7) << 4);
    uint32_t aBase = (uint32_t)rowA * 128;
    uint32_t aColH = ((uint32_t)(lane >> 4) * 16);
    int rowB = wn + (lane & 7) + ((lane >> 4) << 3);
    uint32_t swzB = (uint32_t)((rowB & 7) << 4);
    uint32_t bBase = STG_B + (uint32_t)rowB * 128;
    uint32_t bColH = ((uint32_t)((lane >> 3) & 1) * 16);

    for (int ch = 0; ch < nCh; ch++) {
        asm volatile("cp.async.wait_group 1;");
        __syncthreads();
        if (ch + 2 < nCh) {
            CPST(ch + 2, (ch + 2) % 3);
        } else {
            asm volatile("cp.async.commit_group;");
        }
        uint32_t st = smb + (uint32_t)(ch % 3) * STG;
#pragma unroll
        for (int ks = 0; ks < 2; ks++) {
            uint32_t bh[4][2], bl[4][2], af[4][4];
            uint32_t bcH = ((uint32_t)ks * 32 + bColH) ^ swzB;
            uint32_t bcL = ((uint32_t)ks * 32 + bColH + 64) ^ swzB;
#pragma unroll
            for (int np = 0; np < 2; np++) {
                uint32_t t4[4];
                ldmx4(t4, st + bBase + np * 2048 + bcH);
                bh[2 * np][0] = t4[0]; bh[2 * np][1] = t4[1];
                bh[2 * np + 1][0] = t4[2]; bh[2 * np + 1][1] = t4[3];
                ldmx4(t4, st + bBase + np * 2048 + bcL);
                bl[2 * np][0] = t4[0]; bl[2 * np][1] = t4[1];
                bl[2 * np + 1][0] = t4[2]; bl[2 * np + 1][1] = t4[3];
            }
            uint32_t acH = ((uint32_t)ks * 32 + aColH) ^ swzA;
            uint32_t acL = ((uint32_t)ks * 32 + aColH + 64) ^ swzA;
#pragma unroll
            for (int mt = 0; mt < 4; mt++)
                ldmx4(af[mt], st + aBase + mt * 2048 + acH);
#pragma unroll
            for (int mt = 0; mt < 4; mt++)
#pragma unroll
                for (int nt = 0; nt < 4; nt++) mma16816(acc[mt][nt], af[mt], bh[nt]);
#pragma unroll
            for (int mt = 0; mt < 4; mt++)
#pragma unroll
                for (int nt = 0; nt < 4; nt++) mma16816(acc[mt][nt], af[mt], bl[nt]);
#pragma unroll
            for (int mt = 0; mt < 4; mt++)
                ldmx4(af[mt], st + aBase + mt * 2048 + acL);
#pragma unroll
            for (int mt = 0; mt < 4; mt++)
#pragma unroll
                for (int nt = 0; nt < 4; nt++) mma16816(acc[mt][nt], af[mt], bh[nt]);
        }
    }

    int g = lane >> 2, tg = lane & 3;
#pragma unroll
    for (int mt = 0; mt < 4; mt++) {
        int r0 = i0 + wm + mt * 16 + g;
#pragma unroll
        for (int nt = 0; nt < 4; nt++) {
            int col = j0 + wn + nt * 8 + tg * 2;
            if (r0 < NN)
                *(float2*)(Cout + (size_t)r0 * 512 + col) =
                    make_float2(acc[mt][nt][0], acc[mt][nt][1]);
            if (r0 + 8 < NN)
                *(float2*)(Cout + (size_t)(r0 + 8) * 512 + col) =
                    make_float2(acc[mt][nt][2], acc[mt][nt][3]);
        }
    }
#undef CPST
}

// ---------------- fused GRU + bias fold ----------------
__device__ __forceinline__ float sigf(float x) { return 1.f / (1.f + __expf(-x)); }

__global__ void k_gru(const float* __restrict__ gc, const float* __restrict__ hin,
                      const float* __restrict__ cnt, const float* __restrict__ blw,
                      const float* __restrict__ bih, const float* __restrict__ bhh,
                      float* __restrict__ hout) {
    int idx = blockIdx.x * blockDim.x + threadIdx.x;
    if (idx >= NN * 32) return;
    int i = idx >> 5, c = idx & 31, j = c * 4;
    const float* C = gc + (size_t)i * 512;
    float4 rs4 = *(const float4*)(C + j);
    float4 zs4 = *(const float4*)(C + 128 + j);
    float4 in4 = *(const float4*)(C + 256 + j);
    float4 hn4 = *(const float4*)(C + 384 + j);
    float4 hv4 = *(const float4*)(hin + (size_t)i * DD + j);
    float cn[4] = {cnt[i], cnt[NN + i], cnt[2 * NN + i], cnt[3 * NN + i]};
    float RS[4] = {rs4.x, rs4.y, rs4.z, rs4.w};
    float ZS[4] = {zs4.x, zs4.y, zs4.z, zs4.w};
    float IN[4] = {in4.x, in4.y, in4.z, in4.w};
    float HN[4] = {hn4.x, hn4.y, hn4.z, hn4.w};
    float HH[4] = {hv4.x, hv4.y, hv4.z, hv4.w};
    float o[4];
#pragma unroll
    for (int e = 0; e < 4; e++) {
        int jj = j + e;
        float cr = 0.f, cz = 0.f, cw = 0.f;
#pragma unroll
        for (int k = 0; k < 4; k++) {
            cr += cn[k] * blw[k * 384 + jj];
            cz += cn[k] * blw[k * 384 + 128 + jj];
            cw += cn[k] * blw[k * 384 + 256 + jj];
        }
        float r = sigf(RS[e] + bih[jj] + bhh[jj] + cr);
        float z = sigf(ZS[e] + bih[128 + jj] + bhh[128 + jj] + cz);
        float n = tanhf(IN[e] + bih[256 + jj] + cw + r * (HN[e] + bhh[256 + jj]));
        o[e] = (1.f - z) * n + z * HH[e];
    }
    *(float4*)(hout + (size_t)i * DD + j) = make_float4(o[0], o[1], o[2], o[3]);
}

// ---------------- launch ----------------
extern "C" void kernel_launch(void* const* d_in, const int* in_sizes, int n_in,
                              void* d_out, int out_size) {
    const float* h0 = (const float*)d_in[0];
    const int* src = (const int*)d_in[1];
    const int* dst = (const int*)d_in[2];
    const int* et = (const int*)d_in[3];
    const float* Wlin = (const float*)d_in[4];
    const float* blin = (const float*)d_in[5];
    const float* wih = (const float*)d_in[6];
    const float* whh = (const float*)d_in[7];
    const float* bih = (const float*)d_in[8];
    const float* bhh = (const float*)d_in[9];
    float* out = (float*)d_out;

    float *cnt, *hb, *gcb, *blw;
    __nv_bfloat16 *ah, *al, *whi, *wlo;
    cudaGetSymbolAddress((void**)&cnt, g_cnt);
    cudaGetSymbolAddress((void**)&hb, g_hbuf);
    cudaGetSymbolAddress((void**)&gcb, g_gc);
    cudaGetSymbolAddress((void**)&blw, g_blinw);
    cudaGetSymbolAddress((void**)&ah, g_ah);
    cudaGetSymbolAddress((void**)&al, g_al);
    cudaGetSymbolAddress((void**)&whi, g_wc_hi);
    cudaGetSymbolAddress((void**)&wlo, g_wc_lo);

    cudaFuncSetAttribute(k_gemm, cudaFuncAttributeMaxDynamicSharedMemorySize, SMEM_SZ);

    // launches 1-3; first k_gemm is launch #4 (ncu -s 5 -c 1 captures it)
    k_prep0<<<(247296 + 255) / 256, 256>>>(wih, Wlin, whh, blin);
    k_build<<<(NE + 255) / 256, 256>>>(src, dst, et);

    dim3 gg(4, MT);
    const float* hin = h0;
    for (int s = 0; s < NSTEP; s++) {
        float* hout = (s == NSTEP - 1) ? out : hb + (size_t)(s & 1) * NN * DD;

        k_gather<<<(NN * 32 + 255) / 256, 256>>>(hin);
        k_gemm<<<gg, 256, SMEM_SZ>>>(ah, al, whi, wlo, gcb);
        k_gru<<<(NN * 32 + 255) / 256, 256>>>(gcb, hin, cnt, blw, bih, bhh, hout);
        hin = hout;
    }
}

// round 11
// speedup vs baseline: 1.5748x; 1.5748x over previous
#include <cuda_runtime.h>
#include <cuda_bf16.h>
#include <cstdint>
#include <cstddef>

#define NN 50000
#define NE 600000
#define DD 128
#define NSTEP 5
#define MT 391    // ceil(NN/128)
#define CSTR 128  // padded CSR stride (E[deg]=12)

// ---------------- device scratch ----------------
static __device__ float g_agg[(size_t)4 * NN * DD];
static __device__ float g_cnt[4 * NN];
static __device__ int g_fillc[NN];
static __device__ uint32_t g_csr[(size_t)NN * CSTR];
static __device__ float g_hbuf[(size_t)2 * NN * DD];
static __device__ float g_gc[(size_t)NN * 512];   // [rsum|zsum|i_n|h_n]
static __device__ __align__(16) __nv_bfloat16 g_wc_hi[512 * 640];
static __device__ __align__(16) __nv_bfloat16 g_wc_lo[512 * 640];
static __device__ float g_blinw[4 * 384];

// ---------------- helpers ----------------
__device__ __forceinline__ uint32_t s2u(const void* p) {
    uint32_t a;
    asm("{ .reg .u64 t; cvta.to.shared.u64 t, %1; cvt.u32.u64 %0, t; }" : "=r"(a) : "l"(p));
    return a;
}
__device__ __forceinline__ void cpa16(uint32_t dst, const void* src) {
    asm volatile("cp.async.cg.shared.global [%0], [%1], 16;" :: "r"(dst), "l"(src));
}
__device__ __forceinline__ void ldmx4(uint32_t* r, uint32_t addr) {
    asm volatile("ldmatrix.sync.aligned.m8n8.x4.shared.b16 {%0,%1,%2,%3}, [%4];"
                 : "=r"(r[0]), "=r"(r[1]), "=r"(r[2]), "=r"(r[3]) : "r"(addr));
}
__device__ __forceinline__ void mma16816(float* d, const uint32_t* a, const uint32_t* b) {
    asm volatile(
        "mma.sync.aligned.m16n8k16.row.col.f32.bf16.bf16.f32 "
        "{%0,%1,%2,%3}, {%4,%5,%6,%7}, {%8,%9}, {%0,%1,%2,%3};"
        : "+f"(d[0]), "+f"(d[1]), "+f"(d[2]), "+f"(d[3])
        : "r"(a[0]), "r"(a[1]), "r"(a[2]), "r"(a[3]), "r"(b[0]), "r"(b[1]));
}

// ---------------- launch #1: zero counters + weight precompute ----------------
__global__ void k_prep0(const float* __restrict__ wih, const float* __restrict__ Wlin,
                        const float* __restrict__ whh, const float* __restrict__ blin) {
    int idx = blockIdx.x * blockDim.x + threadIdx.x;
    if (idx < 4 * NN) g_cnt[idx] = 0.f;
    if (idx < NN) g_fillc[idx] = 0;
    if (idx < 196608) {  // Wcomb rows 0-383, cols 0-511: (wih @ Wlin_k), hi/lo
        int j = idx >> 9, kk = idx & 511, kt = kk >> 7, d = kk & 127;
        const float* wr = wih + j * 128;
        const float* wl = Wlin + (size_t)kt * 16384 + d;
        float s = 0.f;
#pragma unroll 8
        for (int d2 = 0; d2 < 128; d2++) s += wr[d2] * wl[(size_t)d2 * 128];
        __nv_bfloat16 h = __float2bfloat16(s);
        g_wc_hi[(size_t)j * 640 + kk] = h;
        g_wc_lo[(size_t)j * 640 + kk] = __float2bfloat16(s - __bfloat162float(h));
        return;
    }
    int t0 = idx - 196608;
    if (t0 < 32768) {            // rows 0-255 (r,z) cols 512-639 <- whh rows 0-255
        int j = t0 >> 7, c = t0 & 127;
        float x = whh[t0];
        __nv_bfloat16 h = __float2bfloat16(x);
        g_wc_hi[(size_t)j * 640 + 512 + c] = h;
        g_wc_lo[(size_t)j * 640 + 512 + c] = __float2bfloat16(x - __bfloat162float(h));
    } else if (t0 < 49152) {     // rows 384-511 (h_n) <- whh rows 256-383
        int t = t0 - 32768;
        int j = t >> 7, c = t & 127;
        float x = whh[(256 + j) * 128 + c];
        __nv_bfloat16 h = __float2bfloat16(x);
        g_wc_hi[(size_t)(384 + j) * 640 + 512 + c] = h;
        g_wc_lo[(size_t)(384 + j) * 640 + 512 + c] =
            __float2bfloat16(x - __bfloat162float(h));
    } else if (t0 < 50688) {     // blw[k][j] = blin[k] . wih[j]
        int t = t0 - 49152;
        int k = t / 384, j = t % 384;
        float s = 0.f;
        for (int d = 0; d < 128; d++) s += blin[k * 128 + d] * wih[j * 128 + d];
        g_blinw[k * 384 + j] = s;
    }
}

// ---------------- launch #2: CSR build + per-type degree counts ----------------
__global__ void k_build(const int* __restrict__ src, const int* __restrict__ dst,
                        const int* __restrict__ et) {
    int e = blockIdx.x * blockDim.x + threadIdx.x;
    if (e >= NE) return;
    int d = dst[e];
    int k = et[e] - 1;
    atomicAdd(&g_cnt[k * NN + d], 1.0f);
    int pos = atomicAdd(&g_fillc[d], 1);
    if (pos < CSTR)
        g_csr[(size_t)d * CSTR + pos] = (uint32_t)src[e] | ((uint32_t)k << 16);
}

// ---------------- per-step gather: warp per node, no atomics ----------------
__global__ __launch_bounds__(256)
void k_gather(const float* __restrict__ h) {
    int v = (blockIdx.x * blockDim.x + threadIdx.x) >> 5;
    int lane = threadIdx.x & 31;
    if (v >= NN) return;
    int deg = g_fillc[v];
    const uint32_t* row = &g_csr[(size_t)v * CSTR];
    const float4* h4 = (const float4*)h;
    float4 a0 = make_float4(0, 0, 0, 0), a1 = a0, a2 = a0, a3 = a0;
    for (int base = 0; base < deg; base += 32) {
        uint32_t pk = (base + lane < deg) ? row[base + lane] : 0u;
        int lim = min(32, deg - base);
        for (int j = 0; j < lim; j++) {
            uint32_t p = __shfl_sync(0xFFFFFFFFu, pk, j);
            int s = p & 0xFFFF;
            int k = p >> 16;
            float4 hv = h4[(size_t)s * 32 + lane];
            switch (k) {
                case 0: a0.x += hv.x; a0.y += hv.y; a0.z += hv.z; a0.w += hv.w; break;
                case 1: a1.x += hv.x; a1.y += hv.y; a1.z += hv.z; a1.w += hv.w; break;
                case 2: a2.x += hv.x; a2.y += hv.y; a2.z += hv.z; a2.w += hv.w; break;
                default: a3.x += hv.x; a3.y += hv.y; a3.z += hv.z; a3.w += hv.w; break;
            }
        }
    }
    float4* o = (float4*)(g_agg + (size_t)v * DD) + lane;
    o[0] = a0;
    o[(size_t)NN * 32] = a1;
    o[(size_t)2 * NN * 32] = a2;
    o[(size_t)3 * NN * 32] = a3;
}

// ---------------- merged 3xBF16 GEMM (R7-proven), 1D long-first grid ----------
// bid < 782: jt = bid&1 (K=640), mt = bid>>1
// bid < 1173: jt = 2 (K=512);  else jt = 3 (K=128) — short CTAs scheduled LAST
#define KC 32
#define RSTR 80
#define A_HALF 10240
#define A_ST_SZ 20480
#define B_BASE 40960
#define B_ST_SZ 20480
#define SMEM_SZ 102400

__global__ __launch_bounds__(256, 2)
void k_gemm(const float* __restrict__ agg, const float* __restrict__ hin,
            const __nv_bfloat16* __restrict__ Whi, const __nv_bfloat16* __restrict__ Wlo,
            float* __restrict__ Cout) {
    extern __shared__ char sm[];
    uint32_t smb = s2u(sm);
    int tid = threadIdx.x, wid = tid >> 5, lane = tid & 31;
    int bid = blockIdx.x;
    int jt, mt;
    if (bid < 782) { jt = bid & 1; mt = bid >> 1; }
    else if (bid < 1173) { jt = 2; mt = bid - 782; }
    else { jt = 3; mt = bid - 1173; }
    int i0 = mt * 128, j0 = jt * 128;
    int kstart = (jt == 3) ? 512 : 0;
    int nCh = (jt == 2) ? 16 : ((jt == 3) ? 4 : 20);
    int wm = (wid & 1) * 64, wn = (wid >> 1) * 32;
    int aRow = tid >> 1, aHalf = tid & 1;
    int gr0 = i0 + aRow;

    float acc[4][4][4];
#pragma unroll
    for (int a = 0; a < 4; a++)
#pragma unroll
        for (int b = 0; b < 4; b++)
#pragma unroll
            for (int c = 0; c < 4; c++) acc[a][b][c] = 0.f;

    float4 av[4];

#define LDG_A(ch)                                                                   \
    {                                                                               \
        int kc_ = kstart + (ch) * KC;                                               \
        int seg_ = kc_ >> 7;                                                        \
        const float* ab_ = (seg_ < 4) ? (agg + (size_t)seg_ * NN * DD) : hin;       \
        if (gr0 < NN) {                                                             \
            const float4* p_ =                                                      \
                (const float4*)(ab_ + (size_t)gr0 * DD + (kc_ & 127) + aHalf * 16); \
            av[0] = p_[0]; av[1] = p_[1]; av[2] = p_[2]; av[3] = p_[3];             \
        } else {                                                                    \
            av[0] = make_float4(0, 0, 0, 0);                                        \
            av[1] = av[0]; av[2] = av[0]; av[3] = av[0];                            \
        }                                                                           \
    }

#define STS_A(buf)                                                                  \
    {                                                                               \
        union { __nv_bfloat16 b[16]; uint4 u[2]; } uh_, ul_;                        \
        const float* f_ = (const float*)av;                                         \
        _Pragma("unroll") for (int i = 0; i < 16; i++) {                            \
            __nv_bfloat16 hv_ = __float2bfloat16(f_[i]);                            \
            uh_.b[i] = hv_;                                                         \
            ul_.b[i] = __float2bfloat16(f_[i] - __bfloat162float(hv_));             \
        }                                                                           \
        uint32_t off_ = (uint32_t)(buf) * A_ST_SZ + aRow * RSTR + aHalf * 32;       \
        *(uint4*)(sm + off_) = uh_.u[0];                                            \
        *(uint4*)(sm + off_ + 16) = uh_.u[1];                                       \
        *(uint4*)(sm + off_ + A_HALF) = ul_.u[0];                                   \
        *(uint4*)(sm + off_ + A_HALF + 16) = ul_.u[1];                              \
    }

#define CP_B(ch, stg)                                                               \
    {                                                                               \
        int kc_ = kstart + (ch) * KC;                                               \
        uint32_t d_ = smb + B_BASE + (uint32_t)(stg) * B_ST_SZ + aRow * RSTR +      \
                      aHalf * 32;                                                   \
        const __nv_bfloat16* sh_ = Whi + (size_t)(j0 + aRow) * 640 + kc_ +          \
                                   aHalf * 16;                                      \
        const __nv_bfloat16* sl_ = Wlo + (size_t)(j0 + aRow) * 640 + kc_ +          \
                                   aHalf * 16;                                      \
        cpa16(d_, sh_);                                                             \
        cpa16(d_ + 16, sh_ + 8);                                                    \
        cpa16(d_ + A_HALF, sl_);                                                    \
        cpa16(d_ + A_HALF + 16, sl_ + 8);                                           \
        asm volatile("cp.async.commit_group;");                                     \
    }

    CP_B(0, 0);
    CP_B(1, 1);
    LDG_A(0);
    STS_A(0);
    LDG_A(1);

    uint32_t aBase = (uint32_t)((wm + (lane & 15)) * RSTR + (lane >> 4) * 16);
    uint32_t bBase = B_BASE +
        (uint32_t)((wn + (lane & 7) + ((lane >> 4) << 3)) * RSTR + ((lane >> 3) & 1) * 16);

    for (int ch = 0; ch < nCh; ch++) {
        asm volatile("cp.async.wait_group 1;");
        __syncthreads();
        if (ch + 2 < nCh) {
            CP_B(ch + 2, (ch + 2) % 3);
        } else {
            asm volatile("cp.async.commit_group;");
        }
        uint32_t sa = smb + (uint32_t)(ch & 1) * A_ST_SZ + aBase;
        uint32_t sb = smb + (uint32_t)(ch % 3) * B_ST_SZ + bBase;
#pragma unroll
        for (int ks = 0; ks < 2; ks++) {
            uint32_t bh[4][2], bl[4][2], af[4][4];
#pragma unroll
            for (int np = 0; np < 2; np++) {
                uint32_t t4[4];
                ldmx4(t4, sb + np * (16 * RSTR) + ks * 32);
                bh[2 * np][0] = t4[0]; bh[2 * np][1] = t4[1];
                bh[2 * np + 1][0] = t4[2]; bh[2 * np + 1][1] = t4[3];
                ldmx4(t4, sb + A_HALF + np * (16 * RSTR) + ks * 32);
                bl[2 * np][0] = t4[0]; bl[2 * np][1] = t4[1];
                bl[2 * np + 1][0] = t4[2]; bl[2 * np + 1][1] = t4[3];
            }
#pragma unroll
            for (int mt2 = 0; mt2 < 4; mt2++)
                ldmx4(af[mt2], sa + mt2 * (16 * RSTR) + ks * 32);
#pragma unroll
            for (int mt2 = 0; mt2 < 4; mt2++)
#pragma unroll
                for (int nt = 0; nt < 4; nt++) mma16816(acc[mt2][nt], af[mt2], bh[nt]);
#pragma unroll
            for (int mt2 = 0; mt2 < 4; mt2++)
#pragma unroll
                for (int nt = 0; nt < 4; nt++) mma16816(acc[mt2][nt], af[mt2], bl[nt]);
#pragma unroll
            for (int mt2 = 0; mt2 < 4; mt2++)
                ldmx4(af[mt2], sa + A_HALF + mt2 * (16 * RSTR) + ks * 32);
#pragma unroll
            for (int mt2 = 0; mt2 < 4; mt2++)
#pragma unroll
                for (int nt = 0; nt < 4; nt++) mma16816(acc[mt2][nt], af[mt2], bh[nt]);
        }
        if (ch + 1 < nCh) { STS_A((ch + 1) & 1); }
        if (ch + 2 < nCh) { LDG_A(ch + 2); }
    }

    int g = lane >> 2, tg = lane & 3;
#pragma unroll
    for (int mt2 = 0; mt2 < 4; mt2++) {
        int r0 = i0 + wm + mt2 * 16 + g;
#pragma unroll
        for (int nt = 0; nt < 4; nt++) {
            int col = j0 + wn + nt * 8 + tg * 2;
            if (r0 < NN)
                *(float2*)(Cout + (size_t)r0 * 512 + col) =
                    make_float2(acc[mt2][nt][0], acc[mt2][nt][1]);
            if (r0 + 8 < NN)
                *(float2*)(Cout + (size_t)(r0 + 8) * 512 + col) =
                    make_float2(acc[mt2][nt][2], acc[mt2][nt][3]);
        }
    }
#undef LDG_A
#undef STS_A
#undef CP_B
}

// ---------------- fused GRU + bias fold ----------------
__device__ __forceinline__ float sigf(float x) { return 1.f / (1.f + __expf(-x)); }

__global__ void k_gru(const float* __restrict__ gc, const float* __restrict__ hin,
                      const float* __restrict__ cnt, const float* __restrict__ blw,
                      const float* __restrict__ bih, const float* __restrict__ bhh,
                      float* __restrict__ hout) {
    int idx = blockIdx.x * blockDim.x + threadIdx.x;
    if (idx >= NN * 32) return;
    int i = idx >> 5, c = idx & 31, j = c * 4;
    const float* C = gc + (size_t)i * 512;
    float4 rs4 = *(const float4*)(C + j);
    float4 zs4 = *(const float4*)(C + 128 + j);
    float4 in4 = *(const float4*)(C + 256 + j);
    float4 hn4 = *(const float4*)(C + 384 + j);
    float4 hv4 = *(const float4*)(hin + (size_t)i * DD + j);
    float cn[4] = {cnt[i], cnt[NN + i], cnt[2 * NN + i], cnt[3 * NN + i]};
    float RS[4] = {rs4.x, rs4.y, rs4.z, rs4.w};
    float ZS[4] = {zs4.x, zs4.y, zs4.z, zs4.w};
    float IN[4] = {in4.x, in4.y, in4.z, in4.w};
    float HN[4] = {hn4.x, hn4.y, hn4.z, hn4.w};
    float HH[4] = {hv4.x, hv4.y, hv4.z, hv4.w};
    float o[4];
#pragma unroll
    for (int e = 0; e < 4; e++) {
        int jj = j + e;
        float cr = 0.f, cz = 0.f, cw = 0.f;
#pragma unroll
        for (int k = 0; k < 4; k++) {
            cr += cn[k] * blw[k * 384 + jj];
            cz += cn[k] * blw[k * 384 + 128 + jj];
            cw += cn[k] * blw[k * 384 + 256 + jj];
        }
        float r = sigf(RS[e] + bih[jj] + bhh[jj] + cr);
        float z = sigf(ZS[e] + bih[128 + jj] + bhh[128 + jj] + cz);
        float n = tanhf(IN[e] + bih[256 + jj] + cw + r * (HN[e] + bhh[256 + jj]));
        o[e] = (1.f - z) * n + z * HH[e];
    }
    *(float4*)(hout + (size_t)i * DD + j) = make_float4(o[0], o[1], o[2], o[3]);
}

// ---------------- launch ----------------
extern "C" void kernel_launch(void* const* d_in, const int* in_sizes, int n_in,
                              void* d_out, int out_size) {
    const float* h0 = (const float*)d_in[0];
    const int* src = (const int*)d_in[1];
    const int* dst = (const int*)d_in[2];
    const int* et = (const int*)d_in[3];
    const float* Wlin = (const float*)d_in[4];
    const float* blin = (const float*)d_in[5];
    const float* wih = (const float*)d_in[6];
    const float* whh = (const float*)d_in[7];
    const float* bih = (const float*)d_in[8];
    const float* bhh = (const float*)d_in[9];
    float* out = (float*)d_out;

    float *agg, *cnt, *hb, *gcb, *blw;
    __nv_bfloat16 *whi, *wlo;
    cudaGetSymbolAddress((void**)&agg, g_agg);
    cudaGetSymbolAddress((void**)&cnt, g_cnt);
    cudaGetSymbolAddress((void**)&hb, g_hbuf);
    cudaGetSymbolAddress((void**)&gcb, g_gc);
    cudaGetSymbolAddress((void**)&blw, g_blinw);
    cudaGetSymbolAddress((void**)&whi, g_wc_hi);
    cudaGetSymbolAddress((void**)&wlo, g_wc_lo);

    cudaFuncSetAttribute(k_gemm, cudaFuncAttributeMaxDynamicSharedMemorySize, SMEM_SZ);

    // launches 1-2; per step: gather, gemm, gru
    k_prep0<<<(247296 + 255) / 256, 256>>>(wih, Wlin, whh, blin);
    k_build<<<(NE + 255) / 256, 256>>>(src, dst, et);

    const float* hin = h0;
    for (int s = 0; s < NSTEP; s++) {
        float* hout = (s == NSTEP - 1) ? out : hb + (size_t)(s & 1) * NN * DD;

        k_gather<<<(NN * 32 + 255) / 256, 256>>>(hin);
        k_gemm<<<1564, 256, SMEM_SZ>>>(agg, hin, whi, wlo, gcb);
        k_gru<<<(NN * 32 + 255) / 256, 256>>>(gcb, hin, cnt, blw, bih, bhh, hout);
        hin = hout;
    }
}